// round 1
// baseline (speedup 1.0000x reference)
#include <cuda_runtime.h>
#include <cuda_bf16.h>
#include <math.h>

#define NN   8192
#define EE   262144
#define INF_ 512
#define HID  512
#define LAT  128

// ---------------- scratch (__device__ globals; no allocation) ----------------
__device__ float g_h0[NN * HID];     // x @ W1
__device__ float g_h[NN * HID];      // relu(agg(h0) + b1)
__device__ float g_agg[NN * HID];    // agg(h)
__device__ float g_dinv[NN];
__device__ int   g_deg[NN];
__device__ int   g_off[NN + 1];
__device__ int   g_cursor[NN];
__device__ int   g_src[EE];

// ---------------- graph preprocessing ----------------
__global__ void zero_kernel() {
    int i = blockIdx.x * blockDim.x + threadIdx.x;
    if (i < NN) { g_deg[i] = 0; g_cursor[i] = 0; }
}

__global__ void count_kernel(const int* __restrict__ col) {
    int e = blockIdx.x * blockDim.x + threadIdx.x;
    if (e < EE) atomicAdd(&g_deg[col[e]], 1);
}

__global__ void dinv_kernel() {
    int i = blockIdx.x * blockDim.x + threadIdx.x;
    if (i < NN) g_dinv[i] = rsqrtf((float)(g_deg[i] + 1));  // +1 self loop
}

// single-block exclusive scan of g_deg -> g_off  (NN = 8192 = 1024 * 8)
__global__ void scan_kernel() {
    __shared__ int s[1024];
    int t = threadIdx.x;
    int base = t * 8;
    int local[8];
    int sum = 0;
    #pragma unroll
    for (int i = 0; i < 8; i++) { local[i] = sum; sum += g_deg[base + i]; }
    s[t] = sum;
    __syncthreads();
    for (int off = 1; off < 1024; off <<= 1) {
        int v = (t >= off) ? s[t - off] : 0;
        __syncthreads();
        s[t] += v;
        __syncthreads();
    }
    int prev = (t > 0) ? s[t - 1] : 0;
    #pragma unroll
    for (int i = 0; i < 8; i++) g_off[base + i] = prev + local[i];
    if (t == 1023) g_off[NN] = s[1023];
}

__global__ void fill_kernel(const int* __restrict__ row, const int* __restrict__ col) {
    int e = blockIdx.x * blockDim.x + threadIdx.x;
    if (e < EE) {
        int c = col[e];
        int pos = g_off[c] + atomicAdd(&g_cursor[c], 1);
        g_src[pos] = row[e];
    }
}

// ---------------- aggregation: out[i] = dinv[i]*sum_{j->i} dinv[j]*H[j] + dinv[i]^2*H[i] ----------------
__global__ void aggregate_kernel(const float* __restrict__ H,
                                 const float* __restrict__ bias,
                                 float* __restrict__ out, int do_relu) {
    int node = blockIdx.x;
    int f = threadIdx.x * 4;               // 128 threads * 4 = 512 features
    float di = g_dinv[node];
    int s0 = g_off[node], s1 = g_off[node + 1];
    float4 acc = make_float4(0.f, 0.f, 0.f, 0.f);
    for (int e = s0; e < s1; e++) {
        int s = g_src[e];
        float w = g_dinv[s];
        float4 v = *(const float4*)&H[(size_t)s * HID + f];
        acc.x += w * v.x; acc.y += w * v.y; acc.z += w * v.z; acc.w += w * v.w;
    }
    float4 hv = *(const float4*)&H[(size_t)node * HID + f];
    float4 r;
    r.x = di * acc.x + di * di * hv.x;
    r.y = di * acc.y + di * di * hv.y;
    r.z = di * acc.z + di * di * hv.z;
    r.w = di * acc.w + di * di * hv.w;
    if (bias) {
        float4 b = *(const float4*)&bias[f];
        r.x += b.x; r.y += b.y; r.z += b.z; r.w += b.w;
    }
    if (do_relu) {
        r.x = fmaxf(r.x, 0.f); r.y = fmaxf(r.y, 0.f);
        r.z = fmaxf(r.z, 0.f); r.w = fmaxf(r.w, 0.f);
    }
    *(float4*)&out[(size_t)node * HID + f] = r;
}

// ---------------- generic tiled SGEMM: C = A(MxK) @ B(KxN) [+bias]; optional dup store ----------------
// 64x64 tile, BK=16, 256 threads, 4x4 microtile. M%64==0, N%64==0, K%16==0.
__global__ void sgemm_kernel(const float* __restrict__ A, const float* __restrict__ B,
                             const float* __restrict__ bias,
                             float* __restrict__ C, float* __restrict__ C2,
                             int M, int Nn, int K) {
    __shared__ float As[16][68];
    __shared__ float Bs[16][68];
    int tid = threadIdx.x;
    int bm = blockIdx.y * 64;
    int bn = blockIdx.x * 64;
    int ty = tid / 16, tx = tid % 16;
    float c[4][4] = {};
    for (int k0 = 0; k0 < K; k0 += 16) {
        // load A tile 64x16 -> As[k][m] (transposed)
        {
            int m = tid / 4, q = tid % 4;
            float4 v = *(const float4*)&A[(size_t)(bm + m) * K + k0 + q * 4];
            As[q * 4 + 0][m] = v.x; As[q * 4 + 1][m] = v.y;
            As[q * 4 + 2][m] = v.z; As[q * 4 + 3][m] = v.w;
        }
        // load B tile 16x64 -> Bs[k][n]
        {
            int r = tid / 16, c4 = tid % 16;
            float4 v = *(const float4*)&B[(size_t)(k0 + r) * Nn + bn + c4 * 4];
            *(float4*)&Bs[r][c4 * 4] = v;
        }
        __syncthreads();
        #pragma unroll
        for (int k = 0; k < 16; k++) {
            float a[4], b[4];
            #pragma unroll
            for (int i = 0; i < 4; i++) a[i] = As[k][ty * 4 + i];
            #pragma unroll
            for (int j = 0; j < 4; j++) b[j] = Bs[k][tx * 4 + j];
            #pragma unroll
            for (int i = 0; i < 4; i++)
                #pragma unroll
                for (int j = 0; j < 4; j++)
                    c[i][j] += a[i] * b[j];
        }
        __syncthreads();
    }
    #pragma unroll
    for (int i = 0; i < 4; i++) {
        int gr = bm + ty * 4 + i;
        #pragma unroll
        for (int j = 0; j < 4; j++) {
            int gc = bn + tx * 4 + j;
            float v = c[i][j];
            if (bias) v += bias[gc];
            C[(size_t)gr * Nn + gc] = v;
            if (C2) C2[(size_t)gr * Nn + gc] = v;
        }
    }
}

// ---------------- A_pred = sigmoid(Z @ Z^T), Z: 8192x128 ----------------
// 128x128 tile, 256 threads, 8x8 microtile, BK=16.
__global__ void zzt_kernel(const float* __restrict__ Z, float* __restrict__ out) {
    const int K = LAT;
    __shared__ float As[16][132];
    __shared__ float Bs[16][132];
    int tid = threadIdx.x;
    int itile = blockIdx.y * 128;
    int jtile = blockIdx.x * 128;
    int ty = tid / 16, tx = tid % 16;
    float c[8][8] = {};
    for (int k0 = 0; k0 < K; k0 += 16) {
        #pragma unroll
        for (int l = 0; l < 2; l++) {
            int idx = tid + l * 256;           // 0..511
            int m = idx / 4, q = idx % 4;
            float4 v = *(const float4*)&Z[(size_t)(itile + m) * K + k0 + q * 4];
            As[q * 4 + 0][m] = v.x; As[q * 4 + 1][m] = v.y;
            As[q * 4 + 2][m] = v.z; As[q * 4 + 3][m] = v.w;
            float4 w = *(const float4*)&Z[(size_t)(jtile + m) * K + k0 + q * 4];
            Bs[q * 4 + 0][m] = w.x; Bs[q * 4 + 1][m] = w.y;
            Bs[q * 4 + 2][m] = w.z; Bs[q * 4 + 3][m] = w.w;
        }
        __syncthreads();
        #pragma unroll
        for (int k = 0; k < 16; k++) {
            float a[8], b[8];
            #pragma unroll
            for (int i = 0; i < 8; i++) a[i] = As[k][ty * 8 + i];
            #pragma unroll
            for (int j = 0; j < 8; j++) b[j] = Bs[k][tx * 8 + j];
            #pragma unroll
            for (int i = 0; i < 8; i++)
                #pragma unroll
                for (int j = 0; j < 8; j++)
                    c[i][j] += a[i] * b[j];
        }
        __syncthreads();
    }
    #pragma unroll
    for (int i = 0; i < 8; i++) {
        size_t gr = itile + ty * 8 + i;
        #pragma unroll
        for (int j = 0; j < 8; j += 4) {
            int gc = jtile + tx * 8 + j;
            float4 v;
            v.x = 1.f / (1.f + __expf(-c[i][j + 0]));
            v.y = 1.f / (1.f + __expf(-c[i][j + 1]));
            v.z = 1.f / (1.f + __expf(-c[i][j + 2]));
            v.w = 1.f / (1.f + __expf(-c[i][j + 3]));
            *(float4*)&out[gr * NN + gc] = v;
        }
    }
}

// ---------------- launch ----------------
extern "C" void kernel_launch(void* const* d_in, const int* in_sizes, int n_in,
                              void* d_out, int out_size) {
    const int*   edge = (const int*)d_in[0];        // [2, E]
    const float* x    = (const float*)d_in[1];      // [N, IN]
    const float* W1   = (const float*)d_in[2];      // [IN, HID]
    const float* b1   = (const float*)d_in[3];
    const float* Wmu  = (const float*)d_in[4];      // [HID, LAT]
    const float* bmu  = (const float*)d_in[5];
    const float* Wlv  = (const float*)d_in[6];
    const float* blv  = (const float*)d_in[7];

    const int* row = edge;
    const int* col = edge + EE;

    float* out     = (float*)d_out;
    float* A_pred  = out;                              // [N, N]
    float* mu_out  = out + (size_t)NN * NN;            // [N, LAT]
    float* lv_out  = mu_out + (size_t)NN * LAT;        // [N, LAT]
    float* z_out   = lv_out + (size_t)NN * LAT;        // [N, LAT]

    float* h0;   cudaGetSymbolAddress((void**)&h0,   g_h0);
    float* h;    cudaGetSymbolAddress((void**)&h,    g_h);
    float* agg;  cudaGetSymbolAddress((void**)&agg,  g_agg);

    // graph preprocessing
    zero_kernel<<<(NN + 255) / 256, 256>>>();
    count_kernel<<<(EE + 255) / 256, 256>>>(col);
    dinv_kernel<<<(NN + 255) / 256, 256>>>();
    scan_kernel<<<1, 1024>>>();
    fill_kernel<<<(EE + 255) / 256, 256>>>(row, col);

    // layer 1: h0 = x @ W1 ; h = relu(agg(h0) + b1)
    sgemm_kernel<<<dim3(HID / 64, NN / 64), 256>>>(x, W1, nullptr, h0, nullptr, NN, HID, INF_);
    aggregate_kernel<<<NN, 128>>>(h0, b1, h, 1);

    // layer 2 shared aggregation: agg = agg(h); mu = agg@Wmu + bmu; logvar = agg@Wlv + blv
    aggregate_kernel<<<NN, 128>>>(h, nullptr, agg, 0);
    sgemm_kernel<<<dim3(LAT / 64, NN / 64), 256>>>(agg, Wmu, bmu, mu_out, z_out, NN, LAT, HID);
    sgemm_kernel<<<dim3(LAT / 64, NN / 64), 256>>>(agg, Wlv, blv, lv_out, nullptr, NN, LAT, HID);

    // decode: A_pred = sigmoid(z z^T)
    zzt_kernel<<<dim3(NN / 128, NN / 128), 256>>>(mu_out, A_pred);
}

// round 3
// speedup vs baseline: 1.5583x; 1.5583x over previous
#include <cuda_runtime.h>
#include <cuda_bf16.h>
#include <math.h>
#include <cstdint>

#define NN   8192
#define EE   262144
#define INF_ 512
#define HID  512
#define LAT  128

// ---------------- scratch (__device__ globals; no allocation) ----------------
__device__ float g_h0[NN * HID];     // x @ W1
__device__ float g_h[NN * HID];      // relu(agg(h0) + b1)
__device__ float g_agg[NN * HID];    // agg(h)
__device__ float g_dinv[NN];
__device__ int   g_deg[NN];
__device__ int   g_off[NN + 1];
__device__ int   g_cursor[NN];
__device__ int   g_src[EE];
__device__ __nv_bfloat16 g_zs[NN * 256];   // bf16 split of z: [:,0:128]=hi, [:,128:256]=lo

__device__ __forceinline__ uint32_t smem_to_u32(const void* smem_ptr) {
    uint32_t addr;
    asm("{ .reg .u64 tmp; cvta.to.shared.u64 tmp, %1; cvt.u32.u64 %0, tmp; }"
        : "=r"(addr) : "l"(smem_ptr));
    return addr;
}

// ---------------- graph preprocessing ----------------
__global__ void zero_kernel() {
    int i = blockIdx.x * blockDim.x + threadIdx.x;
    if (i < NN) { g_deg[i] = 0; g_cursor[i] = 0; }
}

__global__ void count_kernel(const int* __restrict__ col) {
    int e = blockIdx.x * blockDim.x + threadIdx.x;
    if (e < EE) atomicAdd(&g_deg[col[e]], 1);
}

__global__ void dinv_kernel() {
    int i = blockIdx.x * blockDim.x + threadIdx.x;
    if (i < NN) g_dinv[i] = rsqrtf((float)(g_deg[i] + 1));  // +1 self loop
}

// single-block exclusive scan of g_deg -> g_off  (NN = 8192 = 1024 * 8)
__global__ void scan_kernel() {
    __shared__ int s[1024];
    int t = threadIdx.x;
    int base = t * 8;
    int local[8];
    int sum = 0;
    #pragma unroll
    for (int i = 0; i < 8; i++) { local[i] = sum; sum += g_deg[base + i]; }
    s[t] = sum;
    __syncthreads();
    for (int off = 1; off < 1024; off <<= 1) {
        int v = (t >= off) ? s[t - off] : 0;
        __syncthreads();
        s[t] += v;
        __syncthreads();
    }
    int prev = (t > 0) ? s[t - 1] : 0;
    #pragma unroll
    for (int i = 0; i < 8; i++) g_off[base + i] = prev + local[i];
    if (t == 1023) g_off[NN] = s[1023];
}

__global__ void fill_kernel(const int* __restrict__ row, const int* __restrict__ col) {
    int e = blockIdx.x * blockDim.x + threadIdx.x;
    if (e < EE) {
        int c = col[e];
        int pos = g_off[c] + atomicAdd(&g_cursor[c], 1);
        g_src[pos] = row[e];
    }
}

// ---------------- aggregation ----------------
__global__ void aggregate_kernel(const float* __restrict__ H,
                                 const float* __restrict__ bias,
                                 float* __restrict__ out, int do_relu) {
    int node = blockIdx.x;
    int f = threadIdx.x * 4;
    float di = g_dinv[node];
    int s0 = g_off[node], s1 = g_off[node + 1];
    float4 acc = make_float4(0.f, 0.f, 0.f, 0.f);
    for (int e = s0; e < s1; e++) {
        int s = g_src[e];
        float w = g_dinv[s];
        float4 v = *(const float4*)&H[(size_t)s * HID + f];
        acc.x += w * v.x; acc.y += w * v.y; acc.z += w * v.z; acc.w += w * v.w;
    }
    float4 hv = *(const float4*)&H[(size_t)node * HID + f];
    float4 r;
    r.x = di * acc.x + di * di * hv.x;
    r.y = di * acc.y + di * di * hv.y;
    r.z = di * acc.z + di * di * hv.z;
    r.w = di * acc.w + di * di * hv.w;
    if (bias) {
        float4 b = *(const float4*)&bias[f];
        r.x += b.x; r.y += b.y; r.z += b.z; r.w += b.w;
    }
    if (do_relu) {
        r.x = fmaxf(r.x, 0.f); r.y = fmaxf(r.y, 0.f);
        r.z = fmaxf(r.z, 0.f); r.w = fmaxf(r.w, 0.f);
    }
    *(float4*)&out[(size_t)node * HID + f] = r;
}

// ---------------- generic tiled SGEMM ----------------
__global__ void sgemm_kernel(const float* __restrict__ A, const float* __restrict__ B,
                             const float* __restrict__ bias,
                             float* __restrict__ C, float* __restrict__ C2,
                             int M, int Nn, int K) {
    __shared__ float As[16][68];
    __shared__ float Bs[16][68];
    int tid = threadIdx.x;
    int bm = blockIdx.y * 64;
    int bn = blockIdx.x * 64;
    int ty = tid / 16, tx = tid % 16;
    float c[4][4] = {};
    for (int k0 = 0; k0 < K; k0 += 16) {
        {
            int m = tid / 4, q = tid % 4;
            float4 v = *(const float4*)&A[(size_t)(bm + m) * K + k0 + q * 4];
            As[q * 4 + 0][m] = v.x; As[q * 4 + 1][m] = v.y;
            As[q * 4 + 2][m] = v.z; As[q * 4 + 3][m] = v.w;
        }
        {
            int r = tid / 16, c4 = tid % 16;
            float4 v = *(const float4*)&B[(size_t)(k0 + r) * Nn + bn + c4 * 4];
            *(float4*)&Bs[r][c4 * 4] = v;
        }
        __syncthreads();
        #pragma unroll
        for (int k = 0; k < 16; k++) {
            float a[4], b[4];
            #pragma unroll
            for (int i = 0; i < 4; i++) a[i] = As[k][ty * 4 + i];
            #pragma unroll
            for (int j = 0; j < 4; j++) b[j] = Bs[k][tx * 4 + j];
            #pragma unroll
            for (int i = 0; i < 4; i++)
                #pragma unroll
                for (int j = 0; j < 4; j++)
                    c[i][j] += a[i] * b[j];
        }
        __syncthreads();
    }
    #pragma unroll
    for (int i = 0; i < 4; i++) {
        int gr = bm + ty * 4 + i;
        #pragma unroll
        for (int j = 0; j < 4; j++) {
            int gc = bn + tx * 4 + j;
            float v = c[i][j];
            if (bias) v += bias[gc];
            C[(size_t)gr * Nn + gc] = v;
            if (C2) C2[(size_t)gr * Nn + gc] = v;
        }
    }
}

// ---------------- bf16 split ----------------
__global__ void split_kernel(const float* __restrict__ Z, __nv_bfloat16* __restrict__ Zs) {
    int i = blockIdx.x * blockDim.x + threadIdx.x;   // 0 .. N*LAT-1
    float v = Z[i];
    __nv_bfloat16 hi = __float2bfloat16(v);
    float rem = v - __bfloat162float(hi);
    __nv_bfloat16 lo = __float2bfloat16(rem);
    int row = i >> 7, col = i & 127;
    Zs[(size_t)row * 256 + col] = hi;
    Zs[(size_t)row * 256 + 128 + col] = lo;
}

// ---------------- A_pred = sigmoid(Zs @ Zs^T) via mma.sync bf16 ----------------
// CTA: 128x128 output tile, 256 threads = 8 warps (4 m-warps x 2 n-warps).
// Warp tile 32x64. K=256 (hi|lo split), BK=64 chunks through SMEM.
__device__ __forceinline__ void ldsm_x4(uint32_t& r0, uint32_t& r1, uint32_t& r2, uint32_t& r3,
                                        uint32_t addr) {
    asm volatile("ldmatrix.sync.aligned.m8n8.x4.shared.b16 {%0,%1,%2,%3}, [%4];"
                 : "=r"(r0), "=r"(r1), "=r"(r2), "=r"(r3) : "r"(addr));
}

__device__ __forceinline__ void mma_bf16(float* c, const uint32_t* a, const uint32_t* b) {
    asm volatile(
        "mma.sync.aligned.m16n8k16.row.col.f32.bf16.bf16.f32 "
        "{%0,%1,%2,%3}, {%4,%5,%6,%7}, {%8,%9}, {%0,%1,%2,%3};"
        : "+f"(c[0]), "+f"(c[1]), "+f"(c[2]), "+f"(c[3])
        : "r"(a[0]), "r"(a[1]), "r"(a[2]), "r"(a[3]), "r"(b[0]), "r"(b[1]));
}

__global__ __launch_bounds__(256) void zzt_mma_kernel(const __nv_bfloat16* __restrict__ Zs,
                                                      float* __restrict__ out) {
    __shared__ __nv_bfloat16 As[128 * 64];
    __shared__ __nv_bfloat16 Bs[128 * 64];
    int tid = threadIdx.x;
    int wid = tid >> 5;
    int lane = tid & 31;
    int wm = wid & 3;       // warp row: 32 rows each
    int wn = wid >> 2;      // warp col: 64 cols each

    const __nv_bfloat16* Abase = Zs + (size_t)(blockIdx.y * 128) * 256;
    const __nv_bfloat16* Bbase = Zs + (size_t)(blockIdx.x * 128) * 256;
    uint32_t as_u = smem_to_u32(As);
    uint32_t bs_u = smem_to_u32(Bs);

    float acc[2][8][4] = {};

    for (int kc = 0; kc < 4; kc++) {
        // ---- global -> SMEM (swizzled: chunk ^= row&7), 4 x 16B per thread per tile ----
        #pragma unroll
        for (int i = 0; i < 4; i++) {
            int cid = tid + i * 256;          // 0..1023
            int row = cid >> 3;               // 0..127
            int ch = cid & 7;                 // 0..7 (16B chunks within BK=64)
            int sw = (ch ^ (row & 7)) * 8;
            *(float4*)&As[row * 64 + sw] =
                *(const float4*)&Abase[(size_t)row * 256 + kc * 64 + ch * 8];
            *(float4*)&Bs[row * 64 + sw] =
                *(const float4*)&Bbase[(size_t)row * 256 + kc * 64 + ch * 8];
        }
        __syncthreads();

        #pragma unroll
        for (int ks = 0; ks < 4; ks++) {      // K16 steps within chunk
            // A frags: 2 m16 tiles
            uint32_t a[2][4];
            #pragma unroll
            for (int mt = 0; mt < 2; mt++) {
                int row = wm * 32 + mt * 16 + (lane & 15);
                int ch = ks * 2 + (lane >> 4);
                uint32_t addr = as_u + row * 128 + ((ch ^ (row & 7)) << 4);
                ldsm_x4(a[mt][0], a[mt][1], a[mt][2], a[mt][3], addr);
            }
            // B frags: 8 n8 tiles via 4 x ldmatrix.x4 (no trans; [n][k] layout)
            uint32_t b[8][2];
            #pragma unroll
            for (int q = 0; q < 4; q++) {
                int grp = lane >> 3;
                int nrow = wn * 64 + q * 16 + ((grp >> 1) << 3) + (lane & 7);
                int ch = ks * 2 + (grp & 1);
                uint32_t addr = bs_u + nrow * 128 + ((ch ^ (nrow & 7)) << 4);
                ldsm_x4(b[q * 2][0], b[q * 2][1], b[q * 2 + 1][0], b[q * 2 + 1][1], addr);
            }
            #pragma unroll
            for (int mt = 0; mt < 2; mt++)
                #pragma unroll
                for (int nt = 0; nt < 8; nt++)
                    mma_bf16(acc[mt][nt], a[mt], b[nt]);
        }
        __syncthreads();
    }

    // ---- epilogue: sigmoid + store (float2 per thread per tile-row) ----
    int rbase = blockIdx.y * 128 + wm * 32 + (lane >> 2);
    int cbase = blockIdx.x * 128 + wn * 64 + (lane & 3) * 2;
    #pragma unroll
    for (int mt = 0; mt < 2; mt++) {
        #pragma unroll
        for (int nt = 0; nt < 8; nt++) {
            float* c = acc[mt][nt];
            size_t r0 = (size_t)(rbase + mt * 16);
            size_t c0 = (size_t)(cbase + nt * 8);
            float2 v0, v1;
            v0.x = 1.f / (1.f + __expf(-c[0]));
            v0.y = 1.f / (1.f + __expf(-c[1]));
            v1.x = 1.f / (1.f + __expf(-c[2]));
            v1.y = 1.f / (1.f + __expf(-c[3]));
            *(float2*)&out[r0 * NN + c0] = v0;
            *(float2*)&out[(r0 + 8) * NN + c0] = v1;
        }
    }
}

// ---------------- launch ----------------
extern "C" void kernel_launch(void* const* d_in, const int* in_sizes, int n_in,
                              void* d_out, int out_size) {
    const int*   edge = (const int*)d_in[0];
    const float* x    = (const float*)d_in[1];
    const float* W1   = (const float*)d_in[2];
    const float* b1   = (const float*)d_in[3];
    const float* Wmu  = (const float*)d_in[4];
    const float* bmu  = (const float*)d_in[5];
    const float* Wlv  = (const float*)d_in[6];
    const float* blv  = (const float*)d_in[7];

    const int* row = edge;
    const int* col = edge + EE;

    float* out     = (float*)d_out;
    float* A_pred  = out;
    float* mu_out  = out + (size_t)NN * NN;
    float* lv_out  = mu_out + (size_t)NN * LAT;
    float* z_out   = lv_out + (size_t)NN * LAT;

    float* h0;   cudaGetSymbolAddress((void**)&h0,   g_h0);
    float* h;    cudaGetSymbolAddress((void**)&h,    g_h);
    float* agg;  cudaGetSymbolAddress((void**)&agg,  g_agg);
    __nv_bfloat16* zs; cudaGetSymbolAddress((void**)&zs, g_zs);

    // graph preprocessing
    zero_kernel<<<(NN + 255) / 256, 256>>>();
    count_kernel<<<(EE + 255) / 256, 256>>>(col);
    dinv_kernel<<<(NN + 255) / 256, 256>>>();
    scan_kernel<<<1, 1024>>>();
    fill_kernel<<<(EE + 255) / 256, 256>>>(row, col);

    // layer 1: h0 = x @ W1 ; h = relu(agg(h0) + b1)
    sgemm_kernel<<<dim3(HID / 64, NN / 64), 256>>>(x, W1, nullptr, h0, nullptr, NN, HID, INF_);
    aggregate_kernel<<<NN, 128>>>(h0, b1, h, 1);

    // layer 2 shared aggregation
    aggregate_kernel<<<NN, 128>>>(h, nullptr, agg, 0);
    sgemm_kernel<<<dim3(LAT / 64, NN / 64), 256>>>(agg, Wmu, bmu, mu_out, z_out, NN, LAT, HID);
    sgemm_kernel<<<dim3(LAT / 64, NN / 64), 256>>>(agg, Wlv, blv, lv_out, nullptr, NN, LAT, HID);

    // decode: A_pred = sigmoid(z z^T) via bf16-split tensor-core GEMM
    split_kernel<<<(NN * LAT) / 256, 256>>>(mu_out, zs);
    zzt_mma_kernel<<<dim3(NN / 128, NN / 128), 256>>>(zs, A_pred);
}

// round 5
// speedup vs baseline: 2.2185x; 1.4237x over previous
#include <cuda_runtime.h>
#include <cuda_bf16.h>
#include <math.h>
#include <cstdint>

#define NN   8192
#define EE   262144
#define HID  512
#define LAT  128

// ---------------- scratch (__device__ globals; no allocation) ----------------
__device__ float g_h0[NN * HID];                 // x @ W1
__device__ float g_h[NN * HID];                  // relu(agg(h0) + b1)
__device__ float g_dinv[NN];
__device__ int   g_deg[NN];
__device__ int   g_off[NN + 1];
__device__ int   g_cursor[NN];
__device__ int   g_src[EE];
__device__ __nv_bfloat16 g_zs[NN * 128];         // z hi-only bf16
__device__ __nv_bfloat16 g_xs[NN * 1024];        // x split: [:,0:512]=hi, [:,512:1024]=lo
__device__ __nv_bfloat16 g_aggs[NN * 1024];      // agg(h) split
__device__ __nv_bfloat16 g_w1s[512 * 1024];      // W1^T split: [n][k-hi | k-lo]
__device__ __nv_bfloat16 g_wmls[256 * 1024];     // [Wmu^T ; Wlv^T] split

__device__ __forceinline__ uint32_t smem_to_u32(const void* smem_ptr) {
    uint32_t addr;
    asm("{ .reg .u64 tmp; cvta.to.shared.u64 tmp, %1; cvt.u32.u64 %0, tmp; }"
        : "=r"(addr) : "l"(smem_ptr));
    return addr;
}

// ---------------- graph preprocessing ----------------
__global__ void zero_kernel() {
    int i = blockIdx.x * blockDim.x + threadIdx.x;
    if (i < NN) { g_deg[i] = 0; g_cursor[i] = 0; }
}

__global__ void count_kernel(const int* __restrict__ col) {
    int e = blockIdx.x * blockDim.x + threadIdx.x;
    if (e < EE) atomicAdd(&g_deg[col[e]], 1);
}

// warp-shuffle scan of g_deg -> g_off, plus dinv (single block, 1024 threads x 8)
__global__ void scan_kernel() {
    __shared__ int wtot[32];
    int t = threadIdx.x, lane = t & 31, w = t >> 5;
    int base = t * 8;
    int d[8], pre[8];
    int sum = 0;
    #pragma unroll
    for (int i = 0; i < 8; i++) { d[i] = g_deg[base + i]; pre[i] = sum; sum += d[i]; }
    int v = sum;
    #pragma unroll
    for (int off = 1; off < 32; off <<= 1) {
        int n = __shfl_up_sync(0xffffffffu, v, off);
        if (lane >= off) v += n;
    }
    if (lane == 31) wtot[w] = v;
    __syncthreads();
    if (w == 0) {
        int x = wtot[lane];
        int y = x;
        #pragma unroll
        for (int off = 1; off < 32; off <<= 1) {
            int n = __shfl_up_sync(0xffffffffu, y, off);
            if (lane >= off) y += n;
        }
        wtot[lane] = y - x;
    }
    __syncthreads();
    int excl = v - sum + wtot[w];
    #pragma unroll
    for (int i = 0; i < 8; i++) g_off[base + i] = excl + pre[i];
    #pragma unroll
    for (int i = 0; i < 8; i++) g_dinv[base + i] = rsqrtf((float)(d[i] + 1));
    if (t == 1023) g_off[NN] = excl + sum;
}

__global__ void fill_kernel(const int* __restrict__ row, const int* __restrict__ col) {
    int e = blockIdx.x * blockDim.x + threadIdx.x;
    if (e < EE) {
        int c = col[e];
        int pos = g_off[c] + atomicAdd(&g_cursor[c], 1);
        g_src[pos] = row[e];
    }
}

// ---------------- splits ----------------
__device__ __forceinline__ void split2(float v, __nv_bfloat16& hi, __nv_bfloat16& lo) {
    hi = __float2bfloat16(v);
    lo = __float2bfloat16(v - __bfloat162float(hi));
}

__global__ void split_x_kernel(const float* __restrict__ X, __nv_bfloat16* __restrict__ Xs) {
    int i = blockIdx.x * blockDim.x + threadIdx.x;
    int row = i >> 9, k = i & 511;
    __nv_bfloat16 hi, lo;
    split2(X[i], hi, lo);
    Xs[(size_t)row * 1024 + k] = hi;
    Xs[(size_t)row * 1024 + 512 + k] = lo;
}

// W [512,N] -> Ws [N, 512hi | 512lo] (transpose + split)
__global__ void wsplit_kernel(const float* __restrict__ W, __nv_bfloat16* __restrict__ Ws, int N) {
    int i = blockIdx.x * blockDim.x + threadIdx.x;
    int k = i / N, n = i - k * N;
    if (k >= 512) return;
    __nv_bfloat16 hi, lo;
    split2(W[i], hi, lo);
    Ws[(size_t)n * 1024 + k] = hi;
    Ws[(size_t)n * 1024 + 512 + k] = lo;
}

// ---------------- aggregation ----------------
__global__ void aggregate_kernel(const float* __restrict__ H,
                                 const float* __restrict__ bias,
                                 float* __restrict__ out) {
    int node = blockIdx.x;
    int f = threadIdx.x * 4;
    float di = g_dinv[node];
    int s0 = g_off[node], s1 = g_off[node + 1];
    float4 acc = make_float4(0.f, 0.f, 0.f, 0.f);
    for (int e = s0; e < s1; e++) {
        int s = g_src[e];
        float w = g_dinv[s];
        float4 v = *(const float4*)&H[(size_t)s * HID + f];
        acc.x += w * v.x; acc.y += w * v.y; acc.z += w * v.z; acc.w += w * v.w;
    }
    float4 hv = *(const float4*)&H[(size_t)node * HID + f];
    float4 b = *(const float4*)&bias[f];
    float4 r;
    r.x = fmaxf(di * acc.x + di * di * hv.x + b.x, 0.f);
    r.y = fmaxf(di * acc.y + di * di * hv.y + b.y, 0.f);
    r.z = fmaxf(di * acc.z + di * di * hv.z + b.z, 0.f);
    r.w = fmaxf(di * acc.w + di * di * hv.w + b.w, 0.f);
    *(float4*)&out[(size_t)node * HID + f] = r;
}

// pass 2: aggregate + emit bf16 split rows directly
__global__ void aggregate_split_kernel(const float* __restrict__ H,
                                       __nv_bfloat16* __restrict__ outs) {
    int node = blockIdx.x;
    int f = threadIdx.x * 4;
    float di = g_dinv[node];
    int s0 = g_off[node], s1 = g_off[node + 1];
    float4 acc = make_float4(0.f, 0.f, 0.f, 0.f);
    for (int e = s0; e < s1; e++) {
        int s = g_src[e];
        float w = g_dinv[s];
        float4 v = *(const float4*)&H[(size_t)s * HID + f];
        acc.x += w * v.x; acc.y += w * v.y; acc.z += w * v.z; acc.w += w * v.w;
    }
    float4 hv = *(const float4*)&H[(size_t)node * HID + f];
    float r[4];
    r[0] = di * acc.x + di * di * hv.x;
    r[1] = di * acc.y + di * di * hv.y;
    r[2] = di * acc.z + di * di * hv.z;
    r[3] = di * acc.w + di * di * hv.w;
    size_t rb = (size_t)node * 1024 + f;
    #pragma unroll
    for (int j = 0; j < 4; j++) {
        __nv_bfloat16 hi, lo;
        split2(r[j], hi, lo);
        outs[rb + j] = hi;
        outs[rb + 512 + j] = lo;
    }
}

// ---------------- MMA GEMM: C = A @ B^T ----------------
// PHASES==3: split-GEMM hi*hi + hi*lo + lo*hi over [hi|lo] storage (row stride 2*KPART).
// PHASES==1: plain bf16 GEMM (row stride KPART).
// MODE 0: C0 store (ld 512). MODE 1: sigmoid -> C0 (ld NN).
// MODE 2: +bias; gc<128 -> mu(C0)+zdup(C1)+zs-hi; gc>=128 -> lv(C2).
__device__ __forceinline__ void ldsm_x4(uint32_t& r0, uint32_t& r1, uint32_t& r2, uint32_t& r3,
                                        uint32_t addr) {
    asm volatile("ldmatrix.sync.aligned.m8n8.x4.shared.b16 {%0,%1,%2,%3}, [%4];"
                 : "=r"(r0), "=r"(r1), "=r"(r2), "=r"(r3) : "r"(addr));
}

__device__ __forceinline__ void mma_bf16(float* c, const uint32_t* a, const uint32_t* b) {
    asm volatile(
        "mma.sync.aligned.m16n8k16.row.col.f32.bf16.bf16.f32 "
        "{%0,%1,%2,%3}, {%4,%5,%6,%7}, {%8,%9}, {%0,%1,%2,%3};"
        : "+f"(c[0]), "+f"(c[1]), "+f"(c[2]), "+f"(c[3])
        : "r"(a[0]), "r"(a[1]), "r"(a[2]), "r"(a[3]), "r"(b[0]), "r"(b[1]));
}

template<int KPART, int PHASES, int MODE>
__global__ __launch_bounds__(256) void mma_gemm(
    const __nv_bfloat16* __restrict__ A, const __nv_bfloat16* __restrict__ B,
    float* __restrict__ C0, float* __restrict__ C1, float* __restrict__ C2,
    const float* __restrict__ bias0, const float* __restrict__ bias1,
    __nv_bfloat16* __restrict__ zso) {
    constexpr int RS = (PHASES == 3 ? 2 : 1) * KPART;   // row stride (elements)
    constexpr int CPK = KPART / 64;                     // BK chunks per phase
    constexpr int NSTEP = PHASES * CPK;

    __shared__ __nv_bfloat16 As[128 * 64];
    __shared__ __nv_bfloat16 Bs[128 * 64];
    int tid = threadIdx.x;
    int wid = tid >> 5;
    int lane = tid & 31;
    int wm = wid & 3;
    int wn = wid >> 2;

    const __nv_bfloat16* Abase = A + (size_t)(blockIdx.y * 128) * RS;
    const __nv_bfloat16* Bbase = B + (size_t)(blockIdx.x * 128) * RS;
    uint32_t as_u = smem_to_u32(As);
    uint32_t bs_u = smem_to_u32(Bs);

    float acc[2][8][4] = {};

    for (int step = 0; step < NSTEP; step++) {
        int p = step / CPK;
        int kk = step % CPK;
        int aoff = (PHASES == 3 && p == 2) ? KPART : 0;   // phase2: A=lo
        int boff = (PHASES == 3 && p == 1) ? KPART : 0;   // phase1: B=lo
        #pragma unroll
        for (int i = 0; i < 4; i++) {
            int cid = tid + i * 256;
            int row = cid >> 3;
            int ch = cid & 7;
            int sw = (ch ^ (row & 7)) * 8;
            *(float4*)&As[row * 64 + sw] =
                *(const float4*)&Abase[(size_t)row * RS + aoff + kk * 64 + ch * 8];
            *(float4*)&Bs[row * 64 + sw] =
                *(const float4*)&Bbase[(size_t)row * RS + boff + kk * 64 + ch * 8];
        }
        __syncthreads();

        #pragma unroll
        for (int ks = 0; ks < 4; ks++) {
            uint32_t a[2][4];
            #pragma unroll
            for (int mt = 0; mt < 2; mt++) {
                int row = wm * 32 + mt * 16 + (lane & 15);
                int ch = ks * 2 + (lane >> 4);
                uint32_t addr = as_u + row * 128 + ((ch ^ (row & 7)) << 4);
                ldsm_x4(a[mt][0], a[mt][1], a[mt][2], a[mt][3], addr);
            }
            uint32_t b[8][2];
            #pragma unroll
            for (int q = 0; q < 4; q++) {
                int grp = lane >> 3;
                int nrow = wn * 64 + q * 16 + ((grp >> 1) << 3) + (lane & 7);
                int ch = ks * 2 + (grp & 1);
                uint32_t addr = bs_u + nrow * 128 + ((ch ^ (nrow & 7)) << 4);
                ldsm_x4(b[q * 2][0], b[q * 2][1], b[q * 2 + 1][0], b[q * 2 + 1][1], addr);
            }
            #pragma unroll
            for (int mt = 0; mt < 2; mt++)
                #pragma unroll
                for (int nt = 0; nt < 8; nt++)
                    mma_bf16(acc[mt][nt], a[mt], b[nt]);
        }
        __syncthreads();
    }

    int rbase = blockIdx.y * 128 + wm * 32 + (lane >> 2);
    int cloc = wn * 64 + (lane & 3) * 2;
    #pragma unroll
    for (int mt = 0; mt < 2; mt++) {
        #pragma unroll
        for (int nt = 0; nt < 8; nt++) {
            float* c = acc[mt][nt];
            int gc = blockIdx.x * 128 + cloc + nt * 8;
            #pragma unroll
            for (int rr = 0; rr < 2; rr++) {
                size_t row = (size_t)(rbase + mt * 16 + rr * 8);
                float v0 = c[rr * 2 + 0], v1 = c[rr * 2 + 1];
                if (MODE == 0) {
                    *(float2*)&C0[row * 512 + gc] = make_float2(v0, v1);
                } else if (MODE == 1) {
                    float2 v;
                    v.x = 1.f / (1.f + __expf(-v0));
                    v.y = 1.f / (1.f + __expf(-v1));
                    *(float2*)&C0[row * NN + gc] = v;
                } else {
                    if (gc < 128) {
                        v0 += bias0[gc]; v1 += bias0[gc + 1];
                        float2 v = make_float2(v0, v1);
                        *(float2*)&C0[row * LAT + gc] = v;
                        *(float2*)&C1[row * LAT + gc] = v;
                        zso[row * LAT + gc] = __float2bfloat16(v0);
                        zso[row * LAT + gc + 1] = __float2bfloat16(v1);
                    } else {
                        v0 += bias1[gc - 128]; v1 += bias1[gc - 127];
                        *(float2*)&C2[row * LAT + gc - 128] = make_float2(v0, v1);
                    }
                }
            }
        }
    }
}

// ---------------- launch ----------------
extern "C" void kernel_launch(void* const* d_in, const int* in_sizes, int n_in,
                              void* d_out, int out_size) {
    const int*   edge = (const int*)d_in[0];
    const float* x    = (const float*)d_in[1];
    const float* W1   = (const float*)d_in[2];
    const float* b1   = (const float*)d_in[3];
    const float* Wmu  = (const float*)d_in[4];
    const float* bmu  = (const float*)d_in[5];
    const float* Wlv  = (const float*)d_in[6];
    const float* blv  = (const float*)d_in[7];

    const int* row = edge;
    const int* col = edge + EE;

    float* out     = (float*)d_out;
    float* A_pred  = out;
    float* mu_out  = out + (size_t)NN * NN;
    float* lv_out  = mu_out + (size_t)NN * LAT;
    float* z_out   = lv_out + (size_t)NN * LAT;

    float* h0;   cudaGetSymbolAddress((void**)&h0,   g_h0);
    float* h;    cudaGetSymbolAddress((void**)&h,    g_h);
    __nv_bfloat16* zs;   cudaGetSymbolAddress((void**)&zs,   g_zs);
    __nv_bfloat16* xs;   cudaGetSymbolAddress((void**)&xs,   g_xs);
    __nv_bfloat16* aggs; cudaGetSymbolAddress((void**)&aggs, g_aggs);
    __nv_bfloat16* w1s;  cudaGetSymbolAddress((void**)&w1s,  g_w1s);
    __nv_bfloat16* wmls; cudaGetSymbolAddress((void**)&wmls, g_wmls);

    // graph preprocessing
    zero_kernel<<<(NN + 255) / 256, 256>>>();
    count_kernel<<<(EE + 255) / 256, 256>>>(col);
    scan_kernel<<<1, 1024>>>();
    fill_kernel<<<(EE + 255) / 256, 256>>>(row, col);

    // splits
    split_x_kernel<<<(NN * 512) / 256, 256>>>(x, xs);
    wsplit_kernel<<<(512 * 512) / 256, 256>>>(W1, w1s, 512);
    wsplit_kernel<<<(512 * 128) / 256, 256>>>(Wmu, wmls, 128);
    wsplit_kernel<<<(512 * 128) / 256, 256>>>(Wlv, wmls + 128 * 1024, 128);

    // layer 1: h0 = x @ W1 (3-phase split GEMM); h = relu(agg(h0) + b1)
    mma_gemm<512, 3, 0><<<dim3(4, 64), 256>>>(xs, w1s, h0, nullptr, nullptr,
                                              nullptr, nullptr, nullptr);
    aggregate_kernel<<<NN, 128>>>(h0, b1, h);

    // layer 2: aggs = split(agg(h)); [mu|lv] = aggs @ [Wmu|Wlv] + bias (emits zs hi)
    aggregate_split_kernel<<<NN, 128>>>(h, aggs);
    mma_gemm<512, 3, 2><<<dim3(2, 64), 256>>>(aggs, wmls, mu_out, z_out, lv_out,
                                              bmu, blv, zs);

    // decode: A_pred = sigmoid(z z^T), hi-only bf16 (sigmoid saturation hides 2^-9 logit err)
    mma_gemm<128, 1, 1><<<dim3(64, 64), 256>>>(zs, zs, A_pred, nullptr, nullptr,
                                               nullptr, nullptr, nullptr);
}